// round 1
// baseline (speedup 1.0000x reference)
#include <cuda_runtime.h>
#include <cuda_bf16.h>
#include <cstdint>

// Problem constants
namespace {
constexpr int Bc  = 32;
constexpr int Lc  = 4096;
constexpr int Cc  = 512;
constexpr int Hc  = 8;
constexpr int Sc  = 8;
constexpr int NWc = Lc / Sc;       // 512 windows per batch
constexpr int Mc  = Bc * Lc;       // 131072 rows
}

// Scratch (allocation-free rule: __device__ globals)
__device__ float g_q  [(size_t)Mc * Cc];
__device__ float g_k  [(size_t)Mc * Cc];
__device__ float g_v  [(size_t)Mc * Cc];
__device__ float g_att[(size_t)Mc * Cc];

__device__ __forceinline__ void mma_bf16(float c[4], const uint32_t a[4], const uint32_t b[2]) {
    asm volatile(
        "mma.sync.aligned.m16n8k16.row.col.f32.bf16.bf16.f32 "
        "{%0,%1,%2,%3},{%4,%5,%6,%7},{%8,%9},{%0,%1,%2,%3};\n"
        : "+f"(c[0]), "+f"(c[1]), "+f"(c[2]), "+f"(c[3])
        : "r"(a[0]), "r"(a[1]), "r"(a[2]), "r"(a[3]), "r"(b[0]), "r"(b[1]));
}

// C = A(Mc x 512) @ W(512 x 512) + bias, with optional roll on input rows
// (read x[(pos+4) mod L]) and on output rows (write row (pos+4) mod L).
// bf16 hi/lo split: acc += Ahi*Whi + Alo*Whi + Ahi*Wlo  (fp32 accumulate).
template <bool ROLL_IN, bool ROLL_OUT>
__global__ __launch_bounds__(256) void gemm_kernel(
    const float* __restrict__ Ain, const float* __restrict__ W,
    const float* __restrict__ bias, float* __restrict__ Out)
{
    constexpr int BM = 128, BN = 64, BK = 32, LDSH = BK + 8;

    __shared__ __align__(16) __nv_bfloat16 As_hi[BM][LDSH];
    __shared__ __align__(16) __nv_bfloat16 As_lo[BM][LDSH];
    __shared__ __align__(16) __nv_bfloat16 Bs_hi[BN][LDSH];   // stored transposed: [n][k]
    __shared__ __align__(16) __nv_bfloat16 Bs_lo[BN][LDSH];

    const int tid  = threadIdx.x;
    const int lane = tid & 31;
    const int warp = tid >> 5;
    const int grp  = lane >> 2;      // 0..7
    const int tig  = lane & 3;       // 0..3
    const int wm   = warp & 3;       // 4 warps along M
    const int wn   = warp >> 2;      // 2 warps along N
    const int m0   = blockIdx.y * BM;
    const int n0   = blockIdx.x * BN;

    float acc[2][4][4];
    #pragma unroll
    for (int i = 0; i < 2; ++i)
        #pragma unroll
        for (int j = 0; j < 4; ++j)
            #pragma unroll
            for (int t = 0; t < 4; ++t) acc[i][j][t] = 0.f;

    const int a_col  = (tid & 7) * 4;   // 0..28
    const int a_row0 = tid >> 3;        // 0..31
    const int b_n    = (tid & 15) * 4;  // 0..60
    const int b_k0   = tid >> 4;        // 0..15

    for (int k0 = 0; k0 < Cc; k0 += BK) {
        // ---- load A tile (BM x BK), split fp32 -> bf16 hi/lo ----
        #pragma unroll
        for (int p = 0; p < 4; ++p) {
            const int row = p * 32 + a_row0;
            const int rg  = m0 + row;
            size_t src;
            if (ROLL_IN) {
                const int bb  = rg >> 12;          // / L
                const int pos = rg & (Lc - 1);
                src = ((size_t)bb * Lc + ((pos + Sc / 2) & (Lc - 1))) * Cc + k0 + a_col;
            } else {
                src = (size_t)rg * Cc + k0 + a_col;
            }
            const float4 v = *reinterpret_cast<const float4*>(Ain + src);
            const float vv[4] = {v.x, v.y, v.z, v.w};
            #pragma unroll
            for (int i = 0; i < 4; ++i) {
                const __nv_bfloat16 hi = __float2bfloat16(vv[i]);
                As_hi[row][a_col + i] = hi;
                As_lo[row][a_col + i] = __float2bfloat16(vv[i] - __bfloat162float(hi));
            }
        }
        // ---- load W tile (BK x BN), store transposed [n][k], split hi/lo ----
        #pragma unroll
        for (int p = 0; p < 2; ++p) {
            const int kr = p * 16 + b_k0;
            const float4 v = *reinterpret_cast<const float4*>(W + (size_t)(k0 + kr) * Cc + n0 + b_n);
            const float vv[4] = {v.x, v.y, v.z, v.w};
            #pragma unroll
            for (int i = 0; i < 4; ++i) {
                const __nv_bfloat16 hi = __float2bfloat16(vv[i]);
                Bs_hi[b_n + i][kr] = hi;
                Bs_lo[b_n + i][kr] = __float2bfloat16(vv[i] - __bfloat162float(hi));
            }
        }
        __syncthreads();

        #pragma unroll
        for (int kk = 0; kk < BK; kk += 16) {
            uint32_t ah[2][4], al[2][4], bh[4][2], bl[4][2];
            #pragma unroll
            for (int mf = 0; mf < 2; ++mf) {
                const int r = wm * 32 + mf * 16 + grp;
                ah[mf][0] = *reinterpret_cast<const uint32_t*>(&As_hi[r    ][kk + 2 * tig]);
                ah[mf][1] = *reinterpret_cast<const uint32_t*>(&As_hi[r + 8][kk + 2 * tig]);
                ah[mf][2] = *reinterpret_cast<const uint32_t*>(&As_hi[r    ][kk + 2 * tig + 8]);
                ah[mf][3] = *reinterpret_cast<const uint32_t*>(&As_hi[r + 8][kk + 2 * tig + 8]);
                al[mf][0] = *reinterpret_cast<const uint32_t*>(&As_lo[r    ][kk + 2 * tig]);
                al[mf][1] = *reinterpret_cast<const uint32_t*>(&As_lo[r + 8][kk + 2 * tig]);
                al[mf][2] = *reinterpret_cast<const uint32_t*>(&As_lo[r    ][kk + 2 * tig + 8]);
                al[mf][3] = *reinterpret_cast<const uint32_t*>(&As_lo[r + 8][kk + 2 * tig + 8]);
            }
            #pragma unroll
            for (int nf = 0; nf < 4; ++nf) {
                const int cN = wn * 32 + nf * 8 + grp;
                bh[nf][0] = *reinterpret_cast<const uint32_t*>(&Bs_hi[cN][kk + 2 * tig]);
                bh[nf][1] = *reinterpret_cast<const uint32_t*>(&Bs_hi[cN][kk + 2 * tig + 8]);
                bl[nf][0] = *reinterpret_cast<const uint32_t*>(&Bs_lo[cN][kk + 2 * tig]);
                bl[nf][1] = *reinterpret_cast<const uint32_t*>(&Bs_lo[cN][kk + 2 * tig + 8]);
            }
            #pragma unroll
            for (int mf = 0; mf < 2; ++mf)
                #pragma unroll
                for (int nf = 0; nf < 4; ++nf) {
                    mma_bf16(acc[mf][nf], ah[mf], bh[nf]);
                    mma_bf16(acc[mf][nf], al[mf], bh[nf]);
                    mma_bf16(acc[mf][nf], ah[mf], bl[nf]);
                }
        }
        __syncthreads();
    }

    // ---- epilogue: + bias, optional output roll ----
    #pragma unroll
    for (int mf = 0; mf < 2; ++mf) {
        const int r0 = m0 + wm * 32 + mf * 16 + grp;
        #pragma unroll
        for (int half = 0; half < 2; ++half) {
            const int rg = r0 + half * 8;
            size_t dst_row;
            if (ROLL_OUT) {
                const int bb  = rg >> 12;
                const int pos = rg & (Lc - 1);
                dst_row = (size_t)bb * Lc + ((pos + Sc / 2) & (Lc - 1));
            } else {
                dst_row = (size_t)rg;
            }
            #pragma unroll
            for (int nf = 0; nf < 4; ++nf) {
                const int cN = n0 + wn * 32 + nf * 8 + 2 * tig;
                float2 o;
                o.x = acc[mf][nf][half * 2 + 0] + bias[cN];
                o.y = acc[mf][nf][half * 2 + 1] + bias[cN + 1];
                *reinterpret_cast<float2*>(Out + dst_row * Cc + cN) = o;
            }
        }
    }
}

// Windowed attention: one warp per (window, head). S=8, D=64.
// energy = q@k^T / sqrt(512) + rel-pos bias (+ shift mask on last window),
// softmax over keys, out = att@v.
__global__ __launch_bounds__(128) void attn_kernel(
    const float* __restrict__ q, const float* __restrict__ k,
    const float* __restrict__ v, const float* __restrict__ bt,
    float* __restrict__ out)
{
    __shared__ float sq  [4][Sc * 64];
    __shared__ float sk  [4][Sc * 68];   // padded stride: conflict-free energy reads
    __shared__ float sv  [4][Sc * 64];
    __shared__ float satt[4][64];

    const int lane = threadIdx.x & 31;
    const int wid  = threadIdx.x >> 5;
    const int w    = blockIdx.x >> 1;                    // global window id
    const int h    = ((blockIdx.x & 1) << 2) | wid;      // head

    const size_t base = (size_t)w * Sc * Cc + (size_t)h * 64;

    // load q/k/v slices [8 x 64] for this head
    #pragma unroll
    for (int p = 0; p < 4; ++p) {
        const int flat = p * 128 + lane * 4;
        const int i = flat >> 6, d = flat & 63;
        const size_t g = base + (size_t)i * Cc + d;
        *reinterpret_cast<float4*>(&sq[wid][i * 64 + d]) = *reinterpret_cast<const float4*>(q + g);
        *reinterpret_cast<float4*>(&sk[wid][i * 68 + d]) = *reinterpret_cast<const float4*>(k + g);
        *reinterpret_cast<float4*>(&sv[wid][i * 64 + d]) = *reinterpret_cast<const float4*>(v + g);
    }
    __syncwarp();

    // lane -> (rows i0 and i0+4, key j)
    const int i0 = lane >> 3;
    const int j  = lane & 7;
    float e0 = 0.f, e1 = 0.f;
    const float* qr0 = &sq[wid][i0 * 64];
    const float* qr1 = &sq[wid][(i0 + 4) * 64];
    const float* kr  = &sk[wid][j * 68];
    #pragma unroll
    for (int d = 0; d < 64; ++d) {
        const float kv = kr[d];
        e0 = fmaf(qr0[d], kv, e0);
        e1 = fmaf(qr1[d], kv, e1);
    }
    const float scale = 0.044194173824159216f;  // 1/sqrt(512)
    e0 *= scale;
    e1 *= scale;
    e0 += bt[(j - i0 + 7) * Hc + h];
    e1 += bt[(j - i0 + 3) * Hc + h];            // j - (i0+4) + 7

    if ((w & (NWc - 1)) == NWc - 1) {           // last window in each batch: shift mask
        if (j >= 4) e0 -= 100.f;                // rows 0..3 are segment-1 half
        else        e1 -= 100.f;                // rows 4..7 are segment-2 half
    }

    // softmax over j within 8-lane groups
    float m0 = e0, m1 = e1;
    #pragma unroll
    for (int off = 4; off > 0; off >>= 1) {
        m0 = fmaxf(m0, __shfl_xor_sync(0xffffffffu, m0, off));
        m1 = fmaxf(m1, __shfl_xor_sync(0xffffffffu, m1, off));
    }
    float p0 = __expf(e0 - m0), p1 = __expf(e1 - m1);
    float s0 = p0, s1 = p1;
    #pragma unroll
    for (int off = 4; off > 0; off >>= 1) {
        s0 += __shfl_xor_sync(0xffffffffu, s0, off);
        s1 += __shfl_xor_sync(0xffffffffu, s1, off);
    }
    satt[wid][i0 * 8 + j]       = p0 / s0;
    satt[wid][(i0 + 4) * 8 + j] = p1 / s1;
    __syncwarp();

    // out[i][d] = sum_t att[i][t] * v[t][d]; lane covers d=lane and d=lane+32
    #pragma unroll
    for (int i = 0; i < 8; ++i) {
        float a0 = 0.f, a1 = 0.f;
        #pragma unroll
        for (int t = 0; t < 8; ++t) {
            const float a = satt[wid][i * 8 + t];
            a0 = fmaf(a, sv[wid][t * 64 + lane],      a0);
            a1 = fmaf(a, sv[wid][t * 64 + lane + 32], a1);
        }
        out[base + (size_t)i * Cc + lane]      = a0;
        out[base + (size_t)i * Cc + lane + 32] = a1;
    }
}

extern "C" void kernel_launch(void* const* d_in, const int* in_sizes, int n_in,
                              void* d_out, int out_size)
{
    const float* x  = (const float*)d_in[0];
    const float* Wq = (const float*)d_in[1];
    const float* bq = (const float*)d_in[2];
    const float* Wk = (const float*)d_in[3];
    const float* bk = (const float*)d_in[4];
    const float* Wv = (const float*)d_in[5];
    const float* bv = (const float*)d_in[6];
    const float* Wp = (const float*)d_in[7];
    const float* bp = (const float*)d_in[8];
    const float* bt = (const float*)d_in[9];
    float* out = (float*)d_out;

    float *pq, *pk, *pv, *pa;
    cudaGetSymbolAddress((void**)&pq, g_q);
    cudaGetSymbolAddress((void**)&pk, g_k);
    cudaGetSymbolAddress((void**)&pv, g_v);
    cudaGetSymbolAddress((void**)&pa, g_att);

    dim3 grid(Cc / 64, Mc / 128);   // (8, 1024): x-fastest -> same A tile shared in L2
    gemm_kernel<true,  false><<<grid, 256>>>(x,  Wq, bq, pq);
    gemm_kernel<true,  false><<<grid, 256>>>(x,  Wk, bk, pk);
    gemm_kernel<true,  false><<<grid, 256>>>(x,  Wv, bv, pv);
    attn_kernel<<<Bc * NWc * 2, 128>>>(pq, pk, pv, bt, pa);
    gemm_kernel<false, true ><<<grid, 256>>>(pa, Wp, bp, out);
}

// round 3
// speedup vs baseline: 3.3972x; 3.3972x over previous
#include <cuda_runtime.h>
#include <cuda_fp16.h>
#include <cstdint>

namespace {
constexpr int Bc  = 32;
constexpr int Lc  = 4096;
constexpr int Cc  = 512;
constexpr int Hc  = 8;
constexpr int Sc  = 8;
constexpr int NWc = Lc / Sc;
constexpr int Mc  = Bc * Lc;           // 131072
constexpr int NQKV = 3 * Cc;           // 1536
}

// ---------------- scratch (__device__ globals; no allocations) -------------
__device__ __half g_x16 [(size_t)Mc * Cc];          // rolled x, fp16
__device__ __half g_qkv [(size_t)Mc * NQKV];        // fused q|k|v, fp16
__device__ __half g_att [(size_t)Mc * Cc];          // attention out, fp16
__device__ __half g_wt  [(size_t)NQKV * Cc];        // Wq|Wk|Wv transposed [n][k]
__device__ __half g_wpt [(size_t)Cc * Cc];          // Wp transposed
__device__ float  g_bqkv[NQKV];

// ---------------- helpers ---------------------------------------------------
__device__ __forceinline__ uint32_t smem_u32(const void* p) {
    uint32_t a;
    asm("{ .reg .u64 t; cvta.to.shared.u64 t, %1; cvt.u32.u64 %0, t; }" : "=r"(a) : "l"(p));
    return a;
}
#define SW128(off) ((off) ^ (((off) >> 3) & 0x70))

__device__ __forceinline__ void cpa16(uint32_t saddr, const void* g) {
    asm volatile("cp.async.cg.shared.global [%0], [%1], 16;" :: "r"(saddr), "l"(g) : "memory");
}
#define CPA_COMMIT() asm volatile("cp.async.commit_group;" ::: "memory")

__device__ __forceinline__ void ldsm_x4(uint32_t& r0, uint32_t& r1, uint32_t& r2, uint32_t& r3,
                                        uint32_t addr) {
    asm volatile("ldmatrix.sync.aligned.m8n8.x4.shared.b16 {%0,%1,%2,%3}, [%4];"
                 : "=r"(r0), "=r"(r1), "=r"(r2), "=r"(r3) : "r"(addr));
}
__device__ __forceinline__ void mma_fp16(float c[4], const uint32_t a[4], const uint32_t b[2]) {
    asm volatile(
        "mma.sync.aligned.m16n8k16.row.col.f32.f16.f16.f32 "
        "{%0,%1,%2,%3},{%4,%5,%6,%7},{%8,%9},{%0,%1,%2,%3};\n"
        : "+f"(c[0]), "+f"(c[1]), "+f"(c[2]), "+f"(c[3])
        : "r"(a[0]), "r"(a[1]), "r"(a[2]), "r"(a[3]), "r"(b[0]), "r"(b[1]));
}

// ---------------- prep kernels ----------------------------------------------
// Wt[n][k] = fp16(W[k][n]); dst has row stride 512.
__global__ __launch_bounds__(256) void prep_w(
    const float* __restrict__ W, __half* __restrict__ Wt)
{
    __shared__ float t[32][33];
    const int tx = threadIdx.x & 31, ty = threadIdx.x >> 5;
    const int bn = blockIdx.x * 32, bk = blockIdx.y * 32;
    #pragma unroll
    for (int i = 0; i < 32; i += 8)
        t[ty + i][tx] = W[(size_t)(bk + ty + i) * Cc + bn + tx];
    __syncthreads();
    #pragma unroll
    for (int i = 0; i < 32; i += 8)
        Wt[(size_t)(bn + ty + i) * Cc + bk + tx] = __float2half(t[tx][ty + i]);
}

__global__ void concat_bias(const float* __restrict__ b0, const float* __restrict__ b1,
                            const float* __restrict__ b2, float* __restrict__ dst)
{
    const int i = blockIdx.x * 256 + threadIdx.x;
    if (i < NQKV) {
        const float* s = (i < Cc) ? b0 : (i < 2 * Cc) ? b1 : b2;
        dst[i] = s[i & (Cc - 1)];
    }
}

// x rolled left by S/2 -> fp16
__global__ __launch_bounds__(256) void convert_x(
    const float* __restrict__ x, __half* __restrict__ xo)
{
    const size_t idx = (size_t)blockIdx.x * 256 + threadIdx.x;  // 8-elt chunk id
    const int row = (int)(idx >> 6);
    const int c8  = (int)(idx & 63) * 8;
    const int pos = row & (Lc - 1);
    const size_t srow = (size_t)(row & ~(Lc - 1)) + ((pos + Sc / 2) & (Lc - 1));
    const float4* src = reinterpret_cast<const float4*>(x + srow * Cc + c8);
    const float4 v0 = src[0], v1 = src[1];
    __half2 o[4];
    o[0] = __floats2half2_rn(v0.x, v0.y);
    o[1] = __floats2half2_rn(v0.z, v0.w);
    o[2] = __floats2half2_rn(v1.x, v1.y);
    o[3] = __floats2half2_rn(v1.z, v1.w);
    *reinterpret_cast<uint4*>(xo + idx * 8) = *reinterpret_cast<uint4*>(o);
}

// ---------------- HMMA GEMM -------------------------------------------------
// Out[M, Ntot] = A[M,512](fp16) @ Wt[Ntot,512]^T + bias.  BM=BN=128, BK=64,
// 3-stage cp.async, ldmatrix, 256 threads (warps 4x2), warp tile 32x64.
namespace gh {
constexpr int BM = 128, BN = 128, BK = 64;
constexpr int STAGE_A = BM * BK * 2;            // 16 KB
constexpr int STAGE_B = BN * BK * 2;            // 16 KB
constexpr int STAGE   = STAGE_A + STAGE_B;      // 32 KB
constexpr int NSTAGE  = 3;
constexpr int KSTEPS  = Cc / BK;                // 8
constexpr int DYN_SMEM = NSTAGE * STAGE;        // 96 KB
}

template <typename OutT, bool ROLL_OUT>
__global__ __launch_bounds__(256, 2) void gemm_hmma(
    const __half* __restrict__ A, const __half* __restrict__ Wt,
    const float* __restrict__ bias, OutT* __restrict__ Out, int ldn)
{
    using namespace gh;
    extern __shared__ char smem[];
    const uint32_t sbase = smem_u32(smem);

    const int tid  = threadIdx.x;
    const int lane = tid & 31;
    const int warp = tid >> 5;
    const int wm   = warp & 3;
    const int wn   = warp >> 2;
    const int grp  = lane >> 2;
    const int tig  = lane & 3;
    const int m0   = blockIdx.y * BM;
    const int n0   = blockIdx.x * BN;

    // cp.async geometry: 4 A-chunks + 4 B-chunks of 16B per thread per stage
    const int ld_row = tid >> 1;               // 0..127 (2 threads per row)
    const int ld_c0  = (tid & 1) * 4;          // chunk 0..3 or 4..7 within row
    const __half* gA = A  + (size_t)(m0 + ld_row) * Cc + ld_c0 * 8;
    const __half* gB = Wt + (size_t)(n0 + ld_row) * Cc + ld_c0 * 8;

    auto load_stage = [&](int slot, int ks) {
        const uint32_t sA = sbase + slot * STAGE;
        const uint32_t sB = sA + STAGE_A;
        const size_t koff = (size_t)ks * BK;
        #pragma unroll
        for (int i = 0; i < 4; ++i) {
            const uint32_t off = SW128(ld_row * 128 + (ld_c0 + i) * 16);
            cpa16(sA + off, gA + koff + i * 8);
            cpa16(sB + off, gB + koff + i * 8);
        }
    };

    // ldmatrix per-lane address components
    const uint32_t a_row = (uint32_t)(wm * 32 + (lane & 15)) * 128;
    const uint32_t a_kb  = (uint32_t)(lane >> 4) * 16;
    const uint32_t b_row = (uint32_t)(wn * 64 + (lane & 7) + ((lane >> 4) << 3)) * 128;
    const uint32_t b_kb  = (uint32_t)((lane >> 3) & 1) * 16;

    float acc[2][8][4];
    #pragma unroll
    for (int mf = 0; mf < 2; ++mf)
        #pragma unroll
        for (int nf = 0; nf < 8; ++nf)
            #pragma unroll
            for (int t = 0; t < 4; ++t) acc[mf][nf][t] = 0.f;

    load_stage(0, 0); CPA_COMMIT();
    load_stage(1, 1); CPA_COMMIT();

    for (int ks = 0; ks < KSTEPS; ++ks) {
        if (ks == KSTEPS - 1) asm volatile("cp.async.wait_group 0;" ::: "memory");
        else                  asm volatile("cp.async.wait_group 1;" ::: "memory");
        __syncthreads();

        const uint32_t sA = sbase + (ks % NSTAGE) * STAGE;
        const uint32_t sB = sA + STAGE_A;

        #pragma unroll
        for (int kk = 0; kk < BK; kk += 16) {
            uint32_t a[2][4], b[4][4];
            #pragma unroll
            for (int mf = 0; mf < 2; ++mf)
                ldsm_x4(a[mf][0], a[mf][1], a[mf][2], a[mf][3],
                        sA + SW128(a_row + mf * 16 * 128 + a_kb + kk * 2));
            #pragma unroll
            for (int np = 0; np < 4; ++np)
                ldsm_x4(b[np][0], b[np][1], b[np][2], b[np][3],
                        sB + SW128(b_row + np * 16 * 128 + b_kb + kk * 2));
            #pragma unroll
            for (int mf = 0; mf < 2; ++mf)
                #pragma unroll
                for (int nf = 0; nf < 8; ++nf)
                    mma_fp16(acc[mf][nf], a[mf], &b[nf >> 1][(nf & 1) * 2]);
        }
        __syncthreads();
        if (ks + 2 < KSTEPS) { load_stage((ks + 2) % NSTAGE, ks + 2); CPA_COMMIT(); }
    }

    // ---- epilogue: + bias ----
    #pragma unroll
    for (int mf = 0; mf < 2; ++mf) {
        #pragma unroll
        for (int half_ = 0; half_ < 2; ++half_) {
            const int rg = m0 + wm * 32 + mf * 16 + grp + half_ * 8;
            size_t drow;
            if (ROLL_OUT) {
                const int pos = rg & (Lc - 1);
                drow = (size_t)(rg & ~(Lc - 1)) + ((pos + Sc / 2) & (Lc - 1));
            } else {
                drow = (size_t)rg;
            }
            OutT* op = Out + drow * (size_t)ldn + n0;
            #pragma unroll
            for (int nf = 0; nf < 8; ++nf) {
                const int cN = wn * 64 + nf * 8 + 2 * tig;
                const float v0 = acc[mf][nf][half_ * 2 + 0] + bias[n0 + cN];
                const float v1 = acc[mf][nf][half_ * 2 + 1] + bias[n0 + cN + 1];
                if constexpr (sizeof(OutT) == 2) {
                    *reinterpret_cast<__half2*>(op + cN) = __floats2half2_rn(v0, v1);
                } else {
                    float2 o; o.x = v0; o.y = v1;
                    *reinterpret_cast<float2*>(op + cN) = o;
                }
            }
        }
    }
}

// ---------------- windowed attention ---------------------------------------
// qkv fused fp16 [Mc][1536]; q at col h*64, k at +512, v at +1024.
// att out fp16 [Mc][512].
__global__ __launch_bounds__(128) void attn_kernel(
    const __half* __restrict__ qkv, const float* __restrict__ bt,
    __half* __restrict__ att)
{
    __shared__ float sq  [4][Sc * 64];
    __shared__ float sk  [4][Sc * 68];
    __shared__ float sv  [4][Sc * 64];
    __shared__ float satt[4][64];

    const int lane = threadIdx.x & 31;
    const int wid  = threadIdx.x >> 5;
    const int w    = blockIdx.x >> 1;
    const int h    = ((blockIdx.x & 1) << 2) | wid;

    const size_t rowb = (size_t)w * Sc * NQKV + h * 64;

    #pragma unroll
    for (int p = 0; p < 2; ++p) {
        const int c  = p * 32 + lane;       // 0..63
        const int i  = c >> 3;
        const int d8 = (c & 7) * 8;
        const __half* g = qkv + rowb + (size_t)i * NQKV + d8;
        uint4 uq = *reinterpret_cast<const uint4*>(g);
        uint4 uk = *reinterpret_cast<const uint4*>(g + Cc);
        uint4 uv = *reinterpret_cast<const uint4*>(g + 2 * Cc);
        const __half2* hq = reinterpret_cast<const __half2*>(&uq);
        const __half2* hk = reinterpret_cast<const __half2*>(&uk);
        const __half2* hv = reinterpret_cast<const __half2*>(&uv);
        #pragma unroll
        for (int j = 0; j < 4; ++j) {
            const float2 fq = __half22float2(hq[j]);
            const float2 fk = __half22float2(hk[j]);
            const float2 fv = __half22float2(hv[j]);
            sq[wid][i * 64 + d8 + 2 * j]     = fq.x;
            sq[wid][i * 64 + d8 + 2 * j + 1] = fq.y;
            sk[wid][i * 68 + d8 + 2 * j]     = fk.x;
            sk[wid][i * 68 + d8 + 2 * j + 1] = fk.y;
            sv[wid][i * 64 + d8 + 2 * j]     = fv.x;
            sv[wid][i * 64 + d8 + 2 * j + 1] = fv.y;
        }
    }
    __syncwarp();

    const int i0 = lane >> 3;
    const int j  = lane & 7;
    float e0 = 0.f, e1 = 0.f;
    const float* qr0 = &sq[wid][i0 * 64];
    const float* qr1 = &sq[wid][(i0 + 4) * 64];
    const float* kr  = &sk[wid][j * 68];
    #pragma unroll
    for (int d = 0; d < 64; ++d) {
        const float kv = kr[d];
        e0 = fmaf(qr0[d], kv, e0);
        e1 = fmaf(qr1[d], kv, e1);
    }
    const float scale = 0.044194173824159216f;   // 1/sqrt(512)
    e0 = e0 * scale + bt[(j - i0 + 7) * Hc + h];
    e1 = e1 * scale + bt[(j - i0 + 3) * Hc + h];

    if ((w & (NWc - 1)) == NWc - 1) {
        if (j >= 4) e0 -= 100.f;
        else        e1 -= 100.f;
    }

    float m0 = e0, m1 = e1;
    #pragma unroll
    for (int off = 4; off > 0; off >>= 1) {
        m0 = fmaxf(m0, __shfl_xor_sync(0xffffffffu, m0, off));
        m1 = fmaxf(m1, __shfl_xor_sync(0xffffffffu, m1, off));
    }
    float p0 = __expf(e0 - m0), p1 = __expf(e1 - m1);
    float s0 = p0, s1 = p1;
    #pragma unroll
    for (int off = 4; off > 0; off >>= 1) {
        s0 += __shfl_xor_sync(0xffffffffu, s0, off);
        s1 += __shfl_xor_sync(0xffffffffu, s1, off);
    }
    satt[wid][i0 * 8 + j]       = p0 / s0;
    satt[wid][(i0 + 4) * 8 + j] = p1 / s1;
    __syncwarp();

    const size_t ob = (size_t)w * Sc * Cc + h * 64;
    #pragma unroll
    for (int i = 0; i < 8; ++i) {
        float a0 = 0.f, a1 = 0.f;
        #pragma unroll
        for (int t = 0; t < 8; ++t) {
            const float a = satt[wid][i * 8 + t];
            a0 = fmaf(a, sv[wid][t * 64 + lane],      a0);
            a1 = fmaf(a, sv[wid][t * 64 + lane + 32], a1);
        }
        att[ob + (size_t)i * Cc + lane]      = __float2half(a0);
        att[ob + (size_t)i * Cc + lane + 32] = __float2half(a1);
    }
}

// ---------------- launch -----------------------------------------------------
extern "C" void kernel_launch(void* const* d_in, const int* in_sizes, int n_in,
                              void* d_out, int out_size)
{
    const float* x  = (const float*)d_in[0];
    const float* Wq = (const float*)d_in[1];
    const float* bq = (const float*)d_in[2];
    const float* Wk = (const float*)d_in[3];
    const float* bk = (const float*)d_in[4];
    const float* Wv = (const float*)d_in[5];
    const float* bv = (const float*)d_in[6];
    const float* Wp = (const float*)d_in[7];
    const float* bp = (const float*)d_in[8];
    const float* bt = (const float*)d_in[9];
    float* out = (float*)d_out;

    __half *px16, *pqkv, *patt, *pwt, *pwpt;
    float* pbqkv;
    cudaGetSymbolAddress((void**)&px16, g_x16);
    cudaGetSymbolAddress((void**)&pqkv, g_qkv);
    cudaGetSymbolAddress((void**)&patt, g_att);
    cudaGetSymbolAddress((void**)&pwt,  g_wt);
    cudaGetSymbolAddress((void**)&pwpt, g_wpt);
    cudaGetSymbolAddress((void**)&pbqkv, g_bqkv);

    cudaFuncSetAttribute(gemm_hmma<__half, false>,
                         cudaFuncAttributeMaxDynamicSharedMemorySize, gh::DYN_SMEM);
    cudaFuncSetAttribute(gemm_hmma<float, true>,
                         cudaFuncAttributeMaxDynamicSharedMemorySize, gh::DYN_SMEM);

    dim3 tgrid(16, 16);
    prep_w<<<tgrid, 256>>>(Wq, pwt);
    prep_w<<<tgrid, 256>>>(Wk, pwt + (size_t)Cc * Cc);
    prep_w<<<tgrid, 256>>>(Wv, pwt + (size_t)2 * Cc * Cc);
    prep_w<<<tgrid, 256>>>(Wp, pwpt);
    concat_bias<<<6, 256>>>(bq, bk, bv, pbqkv);

    convert_x<<<(Mc * Cc / 8) / 256, 256>>>(x, px16);

    dim3 g1(NQKV / gh::BN, Mc / gh::BM);   // (12, 1024)
    gemm_hmma<__half, false><<<g1, 256, gh::DYN_SMEM>>>(px16, pwt, pbqkv, pqkv, NQKV);

    attn_kernel<<<Bc * NWc * 2, 128>>>(pqkv, bt, patt);

    dim3 g2(Cc / gh::BN, Mc / gh::BM);     // (4, 1024)
    gemm_hmma<float, true><<<g2, 256, gh::DYN_SMEM>>>(patt, pwpt, bp, out, Cc);
}